// round 2
// baseline (speedup 1.0000x reference)
#include <cuda_runtime.h>
#include <math.h>

#define NN 2000
#define BB 64
#define TT 12
#define DD 16
#define HH 64

constexpr int CIN0 = 65;          // C + H
constexpr int CIN1 = 128;         // 2H
constexpr int F0   = BB * CIN0;   // 4160
constexpr int F1   = BB * CIN1;   // 8192
constexpr int KC0  = 3 * CIN0;    // 195
constexpr int KC1  = 3 * CIN1;    // 384

// ---------------- device scratch (static globals; no runtime allocation) ----------------
__device__ float g_A[NN * NN];                       // 16 MB
__device__ float g_gW0[NN * KC0 * 2 * HH];           // 199.7 MB
__device__ float g_uW0[NN * KC0 * HH];               //  99.8 MB
__device__ float g_gW1[NN * KC1 * 2 * HH];           // 393.2 MB
__device__ float g_uW1[NN * KC1 * HH];               // 196.6 MB
__device__ float g_gb0[NN * 2 * HH];
__device__ float g_ub0[NN * HH];
__device__ float g_gb1[NN * 2 * HH];
__device__ float g_ub1[NN * HH];
__device__ float g_xc[NN * F1];                      // 65.5 MB  (x-concat, c-major: [m, c*B+b])
__device__ float g_y1[NN * F1];                      // A @ xc
__device__ float g_y2[NN * F1];                      // 2A@y1 - xc
__device__ float g_zr[NN * 2 * HH * BB];             // gate output [n, o, b]
__device__ float g_h0[NN * HH * BB];                 // layer0 hidden [n, h, b]
__device__ float g_h1[NN * HH * BB];                 // layer1 hidden [n, h, b]

// ---------------- A = softmax(relu(E E^T)) row-wise ----------------
__global__ void __launch_bounds__(256) adj_softmax_kernel(const float* __restrict__ E) {
    __shared__ float row[NN];
    __shared__ float sred[8];
    int n = blockIdx.x, tid = threadIdx.x;
    int lane = tid & 31, wid = tid >> 5;
    float en[DD];
#pragma unroll
    for (int d = 0; d < DD; d++) en[d] = E[n * DD + d];
    float lmax = 0.f;
    for (int m = tid; m < NN; m += 256) {
        const float* em = &E[m * DD];
        float s = 0.f;
#pragma unroll
        for (int d = 0; d < DD; d++) s += en[d] * em[d];
        s = fmaxf(s, 0.f);
        row[m] = s;
        lmax = fmaxf(lmax, s);
    }
#pragma unroll
    for (int off = 16; off; off >>= 1) lmax = fmaxf(lmax, __shfl_xor_sync(0xffffffffu, lmax, off));
    if (lane == 0) sred[wid] = lmax;
    __syncthreads();
    float bmax = sred[0];
#pragma unroll
    for (int w = 1; w < 8; w++) bmax = fmaxf(bmax, sred[w]);
    float lsum = 0.f;
    for (int m = tid; m < NN; m += 256) {
        float e = expf(row[m] - bmax);
        row[m] = e;
        lsum += e;
    }
#pragma unroll
    for (int off = 16; off; off >>= 1) lsum += __shfl_xor_sync(0xffffffffu, lsum, off);
    __syncthreads();
    if (lane == 0) sred[wid] = lsum;
    __syncthreads();
    float bsum = 0.f;
#pragma unroll
    for (int w = 0; w < 8; w++) bsum += sred[w];
    float inv = 1.f / bsum;
    for (int m = tid; m < NN; m += 256) g_A[(size_t)n * NN + m] = row[m] * inv;
}

// ---------------- generic fp32 GEMM: C = alpha * A(MxK) * B(KxNc) + beta * Cs ----------------
// Requirements used here: K % 8 == 0, Nc % 4 == 0, all row pointers float4-aligned.
__global__ void __launch_bounds__(256) sgemm_kernel(
    const float* __restrict__ A, const float* __restrict__ B,
    const float* __restrict__ Cs, float* __restrict__ C,
    int M, int Ncols, int K, int lda, int ldb, int ldc,
    float alpha, float beta)
{
    constexpr int BM = 128, BN = 128, BK = 8;
    __shared__ float As[BK][BM];
    __shared__ float Bs[BK][BN];
    int tid = threadIdx.x;
    int bm = blockIdx.y * BM;
    int bn = blockIdx.x * BN;
    int tx = tid & 15, ty = tid >> 4;

    float acc[8][8];
#pragma unroll
    for (int i = 0; i < 8; i++)
#pragma unroll
        for (int j = 0; j < 8; j++) acc[i][j] = 0.f;

    int arow = tid >> 1;          // 0..127
    int acol = (tid & 1) * 4;     // 0 or 4
    int brow = tid >> 5;          // 0..7
    int bcol = (tid & 31) * 4;    // 0..124
    bool arow_ok = (bm + arow) < M;
    bool bcol_ok = (bn + bcol) < Ncols;

    for (int k0 = 0; k0 < K; k0 += BK) {
        float4 av = make_float4(0.f, 0.f, 0.f, 0.f);
        if (arow_ok) av = *(const float4*)&A[(size_t)(bm + arow) * lda + k0 + acol];
        As[acol + 0][arow] = av.x;
        As[acol + 1][arow] = av.y;
        As[acol + 2][arow] = av.z;
        As[acol + 3][arow] = av.w;
        float4 bv = make_float4(0.f, 0.f, 0.f, 0.f);
        if (bcol_ok) bv = *(const float4*)&B[(size_t)(k0 + brow) * ldb + bn + bcol];
        *(float4*)&Bs[brow][bcol] = bv;
        __syncthreads();
#pragma unroll
        for (int kk = 0; kk < BK; kk++) {
            float a[8], b[8];
            *(float4*)&a[0] = *(const float4*)&As[kk][ty * 8];
            *(float4*)&a[4] = *(const float4*)&As[kk][ty * 8 + 4];
            *(float4*)&b[0] = *(const float4*)&Bs[kk][tx * 8];
            *(float4*)&b[4] = *(const float4*)&Bs[kk][tx * 8 + 4];
#pragma unroll
            for (int i = 0; i < 8; i++)
#pragma unroll
                for (int j = 0; j < 8; j++) acc[i][j] += a[i] * b[j];
        }
        __syncthreads();
    }

#pragma unroll
    for (int i = 0; i < 8; i++) {
        int row = bm + ty * 8 + i;
        if (row >= M) continue;
#pragma unroll
        for (int j = 0; j < 8; j++) {
            int col = bn + tx * 8 + j;
            if (col < Ncols) {
                float v = alpha * acc[i][j];
                if (beta != 0.f) v += beta * Cs[(size_t)row * ldc + col];
                C[(size_t)row * ldc + col] = v;
            }
        }
    }
}

// ---------------- per-node batched GEMM + fused GRU epilogue ----------------
// out[n,o,b] = act( sum_{k,c} Xg_k[n,c,b] * W[n, k*CIN+c, o] + bias[n,o] )
// GATE: sigmoid -> g_zr. UPDATE: tanh -> h = r*h + (1-r)*hc (in place).
template <int CIN, int OUT, bool GATE>
__global__ void __launch_bounds__(256) node_gemm_kernel(
    const float* __restrict__ xg0, const float* __restrict__ xg1, const float* __restrict__ xg2,
    const float* __restrict__ W, const float* __restrict__ bias,
    float* __restrict__ zr, float* __restrict__ h)
{
    constexpr int KC = 3 * CIN;
    constexpr int F = CIN * BB;
    constexpr int OPT = OUT / 16;
    __shared__ float Xs[8][BB];
    __shared__ float Ws[8][OUT];
    int n = blockIdx.x;
    int tid = threadIdx.x;
    int tx = tid & 15, ty = tid >> 4;

    float acc[OPT][4];
#pragma unroll
    for (int oi = 0; oi < OPT; oi++)
#pragma unroll
        for (int bi = 0; bi < 4; bi++) acc[oi][bi] = 0.f;

    for (int rc = 0; rc < KC; rc += 8) {
        // load X chunk (8 x 64)
#pragma unroll
        for (int e = tid; e < 8 * BB; e += 256) {
            int i = e >> 6, b = e & 63;
            int r = rc + i;
            float v = 0.f;
            if (r < KC) {
                int k = r / CIN;
                int c = r - k * CIN;
                const float* base = (k == 0) ? xg0 : ((k == 1) ? xg1 : xg2);
                v = base[(size_t)n * F + c * BB + b];
            }
            Xs[i][b] = v;
        }
        // load W chunk (8 x OUT) via float4
#pragma unroll
        for (int e4 = tid; e4 < 8 * OUT / 4; e4 += 256) {
            int e = e4 * 4;
            int i = e / OUT, o = e % OUT;
            int r = rc + i;
            float4 v = make_float4(0.f, 0.f, 0.f, 0.f);
            if (r < KC) v = *(const float4*)&W[((size_t)n * KC + r) * OUT + o];
            *(float4*)&Ws[i][o] = v;
        }
        __syncthreads();
#pragma unroll
        for (int i = 0; i < 8; i++) {
            float bvals[4];
            *(float4*)&bvals[0] = *(const float4*)&Xs[i][tx * 4];
            float wv[OPT];
#pragma unroll
            for (int q = 0; q < OPT; q += 4)
                *(float4*)&wv[q] = *(const float4*)&Ws[i][ty * OPT + q];
#pragma unroll
            for (int oi = 0; oi < OPT; oi++)
#pragma unroll
                for (int bi = 0; bi < 4; bi++) acc[oi][bi] += wv[oi] * bvals[bi];
        }
        __syncthreads();
    }

#pragma unroll
    for (int oi = 0; oi < OPT; oi++) {
        int o = ty * OPT + oi;
        float bia = bias[(size_t)n * OUT + o];
#pragma unroll
        for (int bi = 0; bi < 4; bi++) {
            int b = tx * 4 + bi;
            float v = acc[oi][bi] + bia;
            if (GATE) {
                float s = 1.f / (1.f + expf(-v));
                zr[((size_t)n * (2 * HH) + o) * BB + b] = s;
            } else {
                float hc = tanhf(v);
                float r = zr[((size_t)n * (2 * HH) + HH + o) * BB + b];
                size_t hi = ((size_t)n * HH + o) * BB + b;
                float hv = h[hi];
                h[hi] = r * hv + (1.f - r) * hc;
            }
        }
    }
}

// ---------------- prep kernels (build xc buffers) ----------------
__global__ void prep_xc0_kernel(const float* __restrict__ src, int t) {
    long idx = (long)blockIdx.x * blockDim.x + threadIdx.x;
    if (idx >= (long)NN * F0) return;
    int m = (int)(idx / F0);
    int col = (int)(idx - (long)m * F0);
    float v;
    if (col < BB) {
        int b = col;
        v = src[((size_t)(b * TT + t)) * NN + m];
    } else {
        v = g_h0[(size_t)m * (HH * BB) + (col - BB)];
    }
    g_xc[idx] = v;
}

__global__ void prep_xc0b_kernel() {   // overwrite h-part with z*h (layer 0)
    long idx = (long)blockIdx.x * blockDim.x + threadIdx.x;
    if (idx >= (long)NN * HH * BB) return;
    int m = (int)(idx >> 12);
    int e = (int)(idx & 4095);
    g_xc[(size_t)m * F0 + BB + e] = g_zr[(size_t)m * (2 * HH * BB) + e] * g_h0[idx];
}

__global__ void prep_xc1_kernel() {    // xc = concat(h0, h1) (layer 1)
    long idx = (long)blockIdx.x * blockDim.x + threadIdx.x;
    if (idx >= (long)NN * F1) return;
    int m = (int)(idx >> 13);
    int e = (int)(idx & 8191);
    float v = (e < HH * BB) ? g_h0[(size_t)m * (HH * BB) + e]
                            : g_h1[(size_t)m * (HH * BB) + (e - HH * BB)];
    g_xc[idx] = v;
}

__global__ void prep_xc1b_kernel() {   // overwrite h-part with z*h (layer 1)
    long idx = (long)blockIdx.x * blockDim.x + threadIdx.x;
    if (idx >= (long)NN * HH * BB) return;
    int m = (int)(idx >> 12);
    int e = (int)(idx & 4095);
    g_xc[(size_t)m * F1 + HH * BB + e] = g_zr[(size_t)m * (2 * HH * BB) + e] * g_h1[idx];
}

// ---------------- final projection ----------------
__global__ void __launch_bounds__(256) final_kernel(
    const float* __restrict__ cw, const float* __restrict__ cb, float* __restrict__ out)
{
    __shared__ float hs[HH * BB];   // [h][b]
    __shared__ float cws[TT * HH];
    __shared__ float cbs[TT];
    int n = blockIdx.x, tid = threadIdx.x;
    for (int e = tid; e < HH * BB; e += 256) hs[e] = g_h1[(size_t)n * HH * BB + e];
    for (int e = tid; e < TT * HH; e += 256) cws[e] = cw[e];
    if (tid < TT) cbs[tid] = cb[tid];
    __syncthreads();
    for (int p = tid; p < BB * TT; p += 256) {
        int b = p / TT, o = p - b * TT;
        float s = cbs[o];
#pragma unroll
        for (int hh2 = 0; hh2 < HH; hh2++) s += hs[hh2 * BB + b] * cws[o * HH + hh2];
        out[((size_t)(b * TT + o)) * NN + n] = s;
    }
}

// ---------------- host orchestration ----------------
static void sgemm(const float* A, const float* B, const float* Cs, float* C,
                  int M, int Nc, int K, int lda, int ldb, int ldc,
                  float alpha, float beta)
{
    dim3 grid((Nc + 127) / 128, (M + 127) / 128);
    sgemm_kernel<<<grid, 256>>>(A, B, Cs, C, M, Nc, K, lda, ldb, ldc, alpha, beta);
}

extern "C" void kernel_launch(void* const* d_in, const int* in_sizes, int n_in,
                              void* d_out, int out_size)
{
    const float* src  = (const float*)d_in[0];
    const float* E    = (const float*)d_in[1];
    const float* gwp0 = (const float*)d_in[2];
    const float* gbp0 = (const float*)d_in[3];
    const float* uwp0 = (const float*)d_in[4];
    const float* ubp0 = (const float*)d_in[5];
    const float* gwp1 = (const float*)d_in[6];
    const float* gbp1 = (const float*)d_in[7];
    const float* uwp1 = (const float*)d_in[8];
    const float* ubp1 = (const float*)d_in[9];
    const float* cw   = (const float*)d_in[10];
    const float* cb   = (const float*)d_in[11];
    float* out = (float*)d_out;

    float *A_, *gW0_, *uW0_, *gW1_, *uW1_, *gb0_, *ub0_, *gb1_, *ub1_;
    float *xc_, *y1_, *y2_, *zr_, *h0_, *h1_;
    cudaGetSymbolAddress((void**)&A_,   g_A);
    cudaGetSymbolAddress((void**)&gW0_, g_gW0);
    cudaGetSymbolAddress((void**)&uW0_, g_uW0);
    cudaGetSymbolAddress((void**)&gW1_, g_gW1);
    cudaGetSymbolAddress((void**)&uW1_, g_uW1);
    cudaGetSymbolAddress((void**)&gb0_, g_gb0);
    cudaGetSymbolAddress((void**)&ub0_, g_ub0);
    cudaGetSymbolAddress((void**)&gb1_, g_gb1);
    cudaGetSymbolAddress((void**)&ub1_, g_ub1);
    cudaGetSymbolAddress((void**)&xc_,  g_xc);
    cudaGetSymbolAddress((void**)&y1_,  g_y1);
    cudaGetSymbolAddress((void**)&y2_,  g_y2);
    cudaGetSymbolAddress((void**)&zr_,  g_zr);
    cudaGetSymbolAddress((void**)&h0_,  g_h0);
    cudaGetSymbolAddress((void**)&h1_,  g_h1);

    // zero hidden states (every call: deterministic)
    cudaMemsetAsync(h0_, 0, (size_t)NN * HH * BB * sizeof(float), 0);
    cudaMemsetAsync(h1_, 0, (size_t)NN * HH * BB * sizeof(float), 0);

    // adjacency
    adj_softmax_kernel<<<NN, 256>>>(E);

    // fold per-node weights / biases:  (N x D) @ (D x KIO)
    sgemm(E, gwp0, gW0_, gW0_, NN, KC0 * 2 * HH, DD, DD, KC0 * 2 * HH, KC0 * 2 * HH, 1.f, 0.f);
    sgemm(E, uwp0, uW0_, uW0_, NN, KC0 * HH,     DD, DD, KC0 * HH,     KC0 * HH,     1.f, 0.f);
    sgemm(E, gwp1, gW1_, gW1_, NN, KC1 * 2 * HH, DD, DD, KC1 * 2 * HH, KC1 * 2 * HH, 1.f, 0.f);
    sgemm(E, uwp1, uW1_, uW1_, NN, KC1 * HH,     DD, DD, KC1 * HH,     KC1 * HH,     1.f, 0.f);
    sgemm(E, gbp0, gb0_, gb0_, NN, 2 * HH, DD, DD, 2 * HH, 2 * HH, 1.f, 0.f);
    sgemm(E, ubp0, ub0_, ub0_, NN, HH,     DD, DD, HH,     HH,     1.f, 0.f);
    sgemm(E, gbp1, gb1_, gb1_, NN, 2 * HH, DD, DD, 2 * HH, 2 * HH, 1.f, 0.f);
    sgemm(E, ubp1, ub1_, ub1_, NN, HH,     DD, DD, HH,     HH,     1.f, 0.f);

    const int PB = 256;
    for (int t = 0; t < TT; t++) {
        // ===== layer 0 =====
        prep_xc0_kernel<<<(int)(((long)NN * F0 + PB - 1) / PB), PB>>>(src, t);
        sgemm(A_, xc_, xc_, y1_, NN, F0, NN, NN, F0, F0, 1.f, 0.f);
        sgemm(A_, y1_, xc_, y2_, NN, F0, NN, NN, F0, F0, 2.f, -1.f);
        node_gemm_kernel<CIN0, 2 * HH, true><<<NN, 256>>>(xc_, y1_, y2_, gW0_, gb0_, zr_, h0_);
        prep_xc0b_kernel<<<(int)(((long)NN * HH * BB + PB - 1) / PB), PB>>>();
        // update gconv: only z*h columns change (x columns of y1/y2 reused)
        sgemm(A_, xc_ + BB, xc_ + BB, y1_ + BB, NN, F0 - BB, NN, NN, F0, F0, 1.f, 0.f);
        sgemm(A_, y1_ + BB, xc_ + BB, y2_ + BB, NN, F0 - BB, NN, NN, F0, F0, 2.f, -1.f);
        node_gemm_kernel<CIN0, HH, false><<<NN, 256>>>(xc_, y1_, y2_, uW0_, ub0_, zr_, h0_);

        // ===== layer 1 =====
        prep_xc1_kernel<<<(int)(((long)NN * F1 + PB - 1) / PB), PB>>>();
        sgemm(A_, xc_, xc_, y1_, NN, F1, NN, NN, F1, F1, 1.f, 0.f);
        sgemm(A_, y1_, xc_, y2_, NN, F1, NN, NN, F1, F1, 2.f, -1.f);
        node_gemm_kernel<CIN1, 2 * HH, true><<<NN, 256>>>(xc_, y1_, y2_, gW1_, gb1_, zr_, h1_);
        prep_xc1b_kernel<<<(int)(((long)NN * HH * BB + PB - 1) / PB), PB>>>();
        sgemm(A_, xc_ + HH * BB, xc_ + HH * BB, y1_ + HH * BB, NN, F1 - HH * BB, NN, NN, F1, F1, 1.f, 0.f);
        sgemm(A_, y1_ + HH * BB, xc_ + HH * BB, y2_ + HH * BB, NN, F1 - HH * BB, NN, NN, F1, F1, 2.f, -1.f);
        node_gemm_kernel<CIN1, HH, false><<<NN, 256>>>(xc_, y1_, y2_, uW1_, ub1_, zr_, h1_);
    }

    final_kernel<<<NN, 256>>>(cw, cb, out);
}

// round 3
// speedup vs baseline: 1.0141x; 1.0141x over previous
#include <cuda_runtime.h>
#include <math.h>

#define NN 2000
#define BB 64
#define TT 12
#define DD 16
#define HH 64

constexpr int CIN0 = 65;          // C + H
constexpr int CIN1 = 128;         // 2H
constexpr int F0   = BB * CIN0;   // 4160
constexpr int F1   = BB * CIN1;   // 8192
constexpr int KC0  = 3 * CIN0;    // 195
constexpr int KC1  = 3 * CIN1;    // 384

// ---------------- packed f32x2 helpers (sm_100+ FFMA2 path) ----------------
typedef unsigned long long u64;

__device__ __forceinline__ u64 pack2(float x, float y) {
    u64 r; asm("mov.b64 %0, {%1,%2};" : "=l"(r) : "f"(x), "f"(y)); return r;
}
__device__ __forceinline__ void unpack2(u64 v, float& x, float& y) {
    asm("mov.b64 {%0,%1}, %2;" : "=f"(x), "=f"(y) : "l"(v));
}
__device__ __forceinline__ void ffma2(u64& d, u64 a, u64 b) {
    asm("fma.rn.f32x2 %0, %1, %2, %0;" : "+l"(d) : "l"(a), "l"(b));
}

// ---------------- device scratch (static globals; no runtime allocation) ----------------
__device__ float g_A[NN * NN];                       // 16 MB
__device__ float g_gW0[NN * KC0 * 2 * HH];
__device__ float g_uW0[NN * KC0 * HH];
__device__ float g_gW1[NN * KC1 * 2 * HH];
__device__ float g_uW1[NN * KC1 * HH];
__device__ float g_gb0[NN * 2 * HH];
__device__ float g_ub0[NN * HH];
__device__ float g_gb1[NN * 2 * HH];
__device__ float g_ub1[NN * HH];
__device__ float g_xc[NN * F1];                      // x-concat, c-major [m, c*B+b]
__device__ float g_y1[NN * F1];
__device__ float g_y2[NN * F1];
__device__ float g_zr[NN * 2 * HH * BB];
__device__ float g_h0[NN * HH * BB];
__device__ float g_h1[NN * HH * BB];

// ---------------- A = softmax(relu(E E^T)) row-wise ----------------
__global__ void __launch_bounds__(256) adj_softmax_kernel(const float* __restrict__ E) {
    __shared__ float row[NN];
    __shared__ float sred[8];
    int n = blockIdx.x, tid = threadIdx.x;
    int lane = tid & 31, wid = tid >> 5;
    float en[DD];
#pragma unroll
    for (int d = 0; d < DD; d++) en[d] = E[n * DD + d];
    float lmax = 0.f;
    for (int m = tid; m < NN; m += 256) {
        const float* em = &E[m * DD];
        float s = 0.f;
#pragma unroll
        for (int d = 0; d < DD; d++) s += en[d] * em[d];
        s = fmaxf(s, 0.f);
        row[m] = s;
        lmax = fmaxf(lmax, s);
    }
#pragma unroll
    for (int off = 16; off; off >>= 1) lmax = fmaxf(lmax, __shfl_xor_sync(0xffffffffu, lmax, off));
    if (lane == 0) sred[wid] = lmax;
    __syncthreads();
    float bmax = sred[0];
#pragma unroll
    for (int w = 1; w < 8; w++) bmax = fmaxf(bmax, sred[w]);
    float lsum = 0.f;
    for (int m = tid; m < NN; m += 256) {
        float e = expf(row[m] - bmax);
        row[m] = e;
        lsum += e;
    }
#pragma unroll
    for (int off = 16; off; off >>= 1) lsum += __shfl_xor_sync(0xffffffffu, lsum, off);
    __syncthreads();
    if (lane == 0) sred[wid] = lsum;
    __syncthreads();
    float bsum = 0.f;
#pragma unroll
    for (int w = 0; w < 8; w++) bsum += sred[w];
    float inv = 1.f / bsum;
    for (int m = tid; m < NN; m += 256) g_A[(size_t)n * NN + m] = row[m] * inv;
}

// ---------------- fp32 GEMM with FFMA2 + double-buffered smem ----------------
// C = alpha * A(MxK) * B(KxNc) + beta * Cs.  K % 8 == 0, Nc % 4 == 0.
__global__ void __launch_bounds__(256) sgemm_kernel(
    const float* __restrict__ A, const float* __restrict__ B,
    const float* __restrict__ Cs, float* __restrict__ C,
    int M, int Ncols, int K, int lda, int ldb, int ldc,
    float alpha, float beta)
{
    constexpr int BM = 128, BN = 128, BK = 8;
    __shared__ float As[2][BK][BM];
    __shared__ float Bs[2][BK][BN];
    int tid = threadIdx.x;
    int bm = blockIdx.y * BM;
    int bn = blockIdx.x * BN;
    int tx = tid & 15, ty = tid >> 4;

    // acc packed over column pairs: acc2[i][p] = (C[i][2p], C[i][2p+1])
    u64 acc2[8][4];
#pragma unroll
    for (int i = 0; i < 8; i++)
#pragma unroll
        for (int p = 0; p < 4; p++) acc2[i][p] = 0ULL;

    int arow = tid >> 1;
    int acol = (tid & 1) * 4;
    int brow = tid >> 5;
    int bcol = (tid & 31) * 4;
    bool arow_ok = (bm + arow) < M;
    bool bcol_ok = (bn + bcol) < Ncols;

    // prologue: load tile 0
    float4 av = make_float4(0.f, 0.f, 0.f, 0.f);
    float4 bv = make_float4(0.f, 0.f, 0.f, 0.f);
    if (arow_ok) av = *(const float4*)&A[(size_t)(bm + arow) * lda + acol];
    if (bcol_ok) bv = *(const float4*)&B[(size_t)brow * ldb + bn + bcol];
    As[0][acol + 0][arow] = av.x;
    As[0][acol + 1][arow] = av.y;
    As[0][acol + 2][arow] = av.z;
    As[0][acol + 3][arow] = av.w;
    *(float4*)&Bs[0][brow][bcol] = bv;
    __syncthreads();

    int buf = 0;
    for (int k0 = 0; k0 < K; k0 += BK) {
        bool more = (k0 + BK) < K;
        if (more) {
            av = make_float4(0.f, 0.f, 0.f, 0.f);
            bv = make_float4(0.f, 0.f, 0.f, 0.f);
            if (arow_ok) av = *(const float4*)&A[(size_t)(bm + arow) * lda + k0 + BK + acol];
            if (bcol_ok) bv = *(const float4*)&B[(size_t)(k0 + BK + brow) * ldb + bn + bcol];
        }
#pragma unroll
        for (int kk = 0; kk < BK; kk++) {
            float a[8];
            *(float4*)&a[0] = *(const float4*)&As[buf][kk][ty * 8];
            *(float4*)&a[4] = *(const float4*)&As[buf][kk][ty * 8 + 4];
            u64 bp[4];
            const u64* bsrc = (const u64*)&Bs[buf][kk][tx * 8];
#pragma unroll
            for (int p = 0; p < 4; p++) bp[p] = bsrc[p];
#pragma unroll
            for (int i = 0; i < 8; i++) {
                u64 ad = pack2(a[i], a[i]);
#pragma unroll
                for (int p = 0; p < 4; p++) ffma2(acc2[i][p], ad, bp[p]);
            }
        }
        if (more) {
            int nb = buf ^ 1;
            As[nb][acol + 0][arow] = av.x;
            As[nb][acol + 1][arow] = av.y;
            As[nb][acol + 2][arow] = av.z;
            As[nb][acol + 3][arow] = av.w;
            *(float4*)&Bs[nb][brow][bcol] = bv;
        }
        __syncthreads();
        buf ^= 1;
    }

#pragma unroll
    for (int i = 0; i < 8; i++) {
        int row = bm + ty * 8 + i;
        if (row >= M) continue;
#pragma unroll
        for (int p = 0; p < 4; p++) {
            float v0, v1;
            unpack2(acc2[i][p], v0, v1);
            int col0 = bn + tx * 8 + 2 * p;
            if (col0 < Ncols) {
                float v = alpha * v0;
                if (beta != 0.f) v += beta * Cs[(size_t)row * ldc + col0];
                C[(size_t)row * ldc + col0] = v;
            }
            if (col0 + 1 < Ncols) {
                float v = alpha * v1;
                if (beta != 0.f) v += beta * Cs[(size_t)row * ldc + col0 + 1];
                C[(size_t)row * ldc + col0 + 1] = v;
            }
        }
    }
}

// ---------------- per-node batched GEMM + fused GRU epilogue (FFMA2) ----------------
// out[n,o,b] = act( sum_{k,c} Xg_k[n,c,b] * W[n, k*CIN+c, o] + bias[n,o] )
template <int CIN, int OUT, bool GATE>
__global__ void __launch_bounds__(256) node_gemm_kernel(
    const float* __restrict__ xg0, const float* __restrict__ xg1, const float* __restrict__ xg2,
    const float* __restrict__ W, const float* __restrict__ bias,
    float* __restrict__ zr, float* __restrict__ h)
{
    constexpr int KC = 3 * CIN;
    constexpr int F = CIN * BB;
    constexpr int OPT = OUT / 16;    // outputs per thread (8 or 4)
    constexpr int OP2 = OPT / 2;     // packed o-pairs
    __shared__ float Xs[8][BB];
    __shared__ float Ws[8][OUT];
    int n = blockIdx.x;
    int tid = threadIdx.x;
    int tx = tid & 15, ty = tid >> 4;

    // acc packed over o-pairs: acc2[p][bi] = (out[2p][bi], out[2p+1][bi])
    u64 acc2[OP2][4];
#pragma unroll
    for (int p = 0; p < OP2; p++)
#pragma unroll
        for (int bi = 0; bi < 4; bi++) acc2[p][bi] = 0ULL;

    for (int rc = 0; rc < KC; rc += 8) {
#pragma unroll
        for (int e = tid; e < 8 * BB; e += 256) {
            int i = e >> 6, b = e & 63;
            int r = rc + i;
            float v = 0.f;
            if (r < KC) {
                int k = r / CIN;
                int c = r - k * CIN;
                const float* base = (k == 0) ? xg0 : ((k == 1) ? xg1 : xg2);
                v = base[(size_t)n * F + c * BB + b];
            }
            Xs[i][b] = v;
        }
#pragma unroll
        for (int e4 = tid; e4 < 8 * OUT / 4; e4 += 256) {
            int e = e4 * 4;
            int i = e / OUT, o = e % OUT;
            int r = rc + i;
            float4 v = make_float4(0.f, 0.f, 0.f, 0.f);
            if (r < KC) v = *(const float4*)&W[((size_t)n * KC + r) * OUT + o];
            *(float4*)&Ws[i][o] = v;
        }
        __syncthreads();
#pragma unroll
        for (int i = 0; i < 8; i++) {
            float bvals[4];
            *(float4*)&bvals[0] = *(const float4*)&Xs[i][tx * 4];
            u64 wp[OP2];
            const u64* wsrc = (const u64*)&Ws[i][ty * OPT];
#pragma unroll
            for (int p = 0; p < OP2; p++) wp[p] = wsrc[p];
#pragma unroll
            for (int bi = 0; bi < 4; bi++) {
                u64 bd = pack2(bvals[bi], bvals[bi]);
#pragma unroll
                for (int p = 0; p < OP2; p++) ffma2(acc2[p][bi], wp[p], bd);
            }
        }
        __syncthreads();
    }

#pragma unroll
    for (int p = 0; p < OP2; p++) {
        int o0 = ty * OPT + 2 * p;
        float bia0 = bias[(size_t)n * OUT + o0];
        float bia1 = bias[(size_t)n * OUT + o0 + 1];
#pragma unroll
        for (int bi = 0; bi < 4; bi++) {
            int b = tx * 4 + bi;
            float v0, v1;
            unpack2(acc2[p][bi], v0, v1);
            v0 += bia0; v1 += bia1;
            if (GATE) {
                zr[((size_t)n * (2 * HH) + o0) * BB + b]     = 1.f / (1.f + expf(-v0));
                zr[((size_t)n * (2 * HH) + o0 + 1) * BB + b] = 1.f / (1.f + expf(-v1));
            } else {
                float hc0 = tanhf(v0);
                float hc1 = tanhf(v1);
                float r0 = zr[((size_t)n * (2 * HH) + HH + o0) * BB + b];
                float r1 = zr[((size_t)n * (2 * HH) + HH + o0 + 1) * BB + b];
                size_t hi0 = ((size_t)n * HH + o0) * BB + b;
                size_t hi1 = ((size_t)n * HH + o0 + 1) * BB + b;
                float hv0 = h[hi0], hv1 = h[hi1];
                h[hi0] = r0 * hv0 + (1.f - r0) * hc0;
                h[hi1] = r1 * hv1 + (1.f - r1) * hc1;
            }
        }
    }
}

// ---------------- prep kernels (build xc buffers) ----------------
__global__ void prep_xc0_kernel(const float* __restrict__ src, int t) {
    long idx = (long)blockIdx.x * blockDim.x + threadIdx.x;
    if (idx >= (long)NN * F0) return;
    int m = (int)(idx / F0);
    int col = (int)(idx - (long)m * F0);
    float v;
    if (col < BB) {
        int b = col;
        v = src[((size_t)(b * TT + t)) * NN + m];
    } else {
        v = g_h0[(size_t)m * (HH * BB) + (col - BB)];
    }
    g_xc[idx] = v;
}

__global__ void prep_xc0b_kernel() {
    long idx = (long)blockIdx.x * blockDim.x + threadIdx.x;
    if (idx >= (long)NN * HH * BB) return;
    int m = (int)(idx >> 12);
    int e = (int)(idx & 4095);
    g_xc[(size_t)m * F0 + BB + e] = g_zr[(size_t)m * (2 * HH * BB) + e] * g_h0[idx];
}

__global__ void prep_xc1_kernel() {
    long idx = (long)blockIdx.x * blockDim.x + threadIdx.x;
    if (idx >= (long)NN * F1) return;
    int m = (int)(idx >> 13);
    int e = (int)(idx & 8191);
    float v = (e < HH * BB) ? g_h0[(size_t)m * (HH * BB) + e]
                            : g_h1[(size_t)m * (HH * BB) + (e - HH * BB)];
    g_xc[idx] = v;
}

__global__ void prep_xc1b_kernel() {
    long idx = (long)blockIdx.x * blockDim.x + threadIdx.x;
    if (idx >= (long)NN * HH * BB) return;
    int m = (int)(idx >> 12);
    int e = (int)(idx & 4095);
    g_xc[(size_t)m * F1 + HH * BB + e] = g_zr[(size_t)m * (2 * HH * BB) + e] * g_h1[idx];
}

// ---------------- final projection ----------------
__global__ void __launch_bounds__(256) final_kernel(
    const float* __restrict__ cw, const float* __restrict__ cb, float* __restrict__ out)
{
    __shared__ float hs[HH * BB];
    __shared__ float cws[TT * HH];
    __shared__ float cbs[TT];
    int n = blockIdx.x, tid = threadIdx.x;
    for (int e = tid; e < HH * BB; e += 256) hs[e] = g_h1[(size_t)n * HH * BB + e];
    for (int e = tid; e < TT * HH; e += 256) cws[e] = cw[e];
    if (tid < TT) cbs[tid] = cb[tid];
    __syncthreads();
    for (int p = tid; p < BB * TT; p += 256) {
        int b = p / TT, o = p - b * TT;
        float s = cbs[o];
#pragma unroll
        for (int hh2 = 0; hh2 < HH; hh2++) s += hs[hh2 * BB + b] * cws[o * HH + hh2];
        out[((size_t)(b * TT + o)) * NN + n] = s;
    }
}

// ---------------- host orchestration ----------------
static void sgemm(const float* A, const float* B, const float* Cs, float* C,
                  int M, int Nc, int K, int lda, int ldb, int ldc,
                  float alpha, float beta)
{
    dim3 grid((Nc + 127) / 128, (M + 127) / 128);
    sgemm_kernel<<<grid, 256>>>(A, B, Cs, C, M, Nc, K, lda, ldb, ldc, alpha, beta);
}

extern "C" void kernel_launch(void* const* d_in, const int* in_sizes, int n_in,
                              void* d_out, int out_size)
{
    const float* src  = (const float*)d_in[0];
    const float* E    = (const float*)d_in[1];
    const float* gwp0 = (const float*)d_in[2];
    const float* gbp0 = (const float*)d_in[3];
    const float* uwp0 = (const float*)d_in[4];
    const float* ubp0 = (const float*)d_in[5];
    const float* gwp1 = (const float*)d_in[6];
    const float* gbp1 = (const float*)d_in[7];
    const float* uwp1 = (const float*)d_in[8];
    const float* ubp1 = (const float*)d_in[9];
    const float* cw   = (const float*)d_in[10];
    const float* cb   = (const float*)d_in[11];
    float* out = (float*)d_out;

    float *A_, *gW0_, *uW0_, *gW1_, *uW1_, *gb0_, *ub0_, *gb1_, *ub1_;
    float *xc_, *y1_, *y2_, *zr_, *h0_, *h1_;
    cudaGetSymbolAddress((void**)&A_,   g_A);
    cudaGetSymbolAddress((void**)&gW0_, g_gW0);
    cudaGetSymbolAddress((void**)&uW0_, g_uW0);
    cudaGetSymbolAddress((void**)&gW1_, g_gW1);
    cudaGetSymbolAddress((void**)&uW1_, g_uW1);
    cudaGetSymbolAddress((void**)&gb0_, g_gb0);
    cudaGetSymbolAddress((void**)&ub0_, g_ub0);
    cudaGetSymbolAddress((void**)&gb1_, g_gb1);
    cudaGetSymbolAddress((void**)&ub1_, g_ub1);
    cudaGetSymbolAddress((void**)&xc_,  g_xc);
    cudaGetSymbolAddress((void**)&y1_,  g_y1);
    cudaGetSymbolAddress((void**)&y2_,  g_y2);
    cudaGetSymbolAddress((void**)&zr_,  g_zr);
    cudaGetSymbolAddress((void**)&h0_,  g_h0);
    cudaGetSymbolAddress((void**)&h1_,  g_h1);

    cudaMemsetAsync(h0_, 0, (size_t)NN * HH * BB * sizeof(float), 0);
    cudaMemsetAsync(h1_, 0, (size_t)NN * HH * BB * sizeof(float), 0);

    adj_softmax_kernel<<<NN, 256>>>(E);

    sgemm(E, gwp0, gW0_, gW0_, NN, KC0 * 2 * HH, DD, DD, KC0 * 2 * HH, KC0 * 2 * HH, 1.f, 0.f);
    sgemm(E, uwp0, uW0_, uW0_, NN, KC0 * HH,     DD, DD, KC0 * HH,     KC0 * HH,     1.f, 0.f);
    sgemm(E, gwp1, gW1_, gW1_, NN, KC1 * 2 * HH, DD, DD, KC1 * 2 * HH, KC1 * 2 * HH, 1.f, 0.f);
    sgemm(E, uwp1, uW1_, uW1_, NN, KC1 * HH,     DD, DD, KC1 * HH,     KC1 * HH,     1.f, 0.f);
    sgemm(E, gbp0, gb0_, gb0_, NN, 2 * HH, DD, DD, 2 * HH, 2 * HH, 1.f, 0.f);
    sgemm(E, ubp0, ub0_, ub0_, NN, HH,     DD, DD, HH,     HH,     1.f, 0.f);
    sgemm(E, gbp1, gb1_, gb1_, NN, 2 * HH, DD, DD, 2 * HH, 2 * HH, 1.f, 0.f);
    sgemm(E, ubp1, ub1_, ub1_, NN, HH,     DD, DD, HH,     HH,     1.f, 0.f);

    const int PB = 256;
    for (int t = 0; t < TT; t++) {
        // ===== layer 0 =====
        prep_xc0_kernel<<<(int)(((long)NN * F0 + PB - 1) / PB), PB>>>(src, t);
        sgemm(A_, xc_, xc_, y1_, NN, F0, NN, NN, F0, F0, 1.f, 0.f);
        sgemm(A_, y1_, xc_, y2_, NN, F0, NN, NN, F0, F0, 2.f, -1.f);
        node_gemm_kernel<CIN0, 2 * HH, true><<<NN, 256>>>(xc_, y1_, y2_, gW0_, gb0_, zr_, h0_);
        prep_xc0b_kernel<<<(int)(((long)NN * HH * BB + PB - 1) / PB), PB>>>();
        sgemm(A_, xc_ + BB, xc_ + BB, y1_ + BB, NN, F0 - BB, NN, NN, F0, F0, 1.f, 0.f);
        sgemm(A_, y1_ + BB, xc_ + BB, y2_ + BB, NN, F0 - BB, NN, NN, F0, F0, 2.f, -1.f);
        node_gemm_kernel<CIN0, HH, false><<<NN, 256>>>(xc_, y1_, y2_, uW0_, ub0_, zr_, h0_);

        // ===== layer 1 =====
        prep_xc1_kernel<<<(int)(((long)NN * F1 + PB - 1) / PB), PB>>>();
        sgemm(A_, xc_, xc_, y1_, NN, F1, NN, NN, F1, F1, 1.f, 0.f);
        sgemm(A_, y1_, xc_, y2_, NN, F1, NN, NN, F1, F1, 2.f, -1.f);
        node_gemm_kernel<CIN1, 2 * HH, true><<<NN, 256>>>(xc_, y1_, y2_, gW1_, gb1_, zr_, h1_);
        prep_xc1b_kernel<<<(int)(((long)NN * HH * BB + PB - 1) / PB), PB>>>();
        sgemm(A_, xc_ + HH * BB, xc_ + HH * BB, y1_ + HH * BB, NN, F1 - HH * BB, NN, NN, F1, F1, 1.f, 0.f);
        sgemm(A_, y1_ + HH * BB, xc_ + HH * BB, y2_ + HH * BB, NN, F1 - HH * BB, NN, NN, F1, F1, 2.f, -1.f);
        node_gemm_kernel<CIN1, HH, false><<<NN, 256>>>(xc_, y1_, y2_, uW1_, ub1_, zr_, h1_);
    }

    final_kernel<<<NN, 256>>>(cw, cb, out);
}

// round 4
// speedup vs baseline: 1.0150x; 1.0009x over previous
#include <cuda_runtime.h>
#include <math.h>

#define NN 2000
#define BB 64
#define TT 12
#define DD 16
#define HH 64

constexpr int CIN0 = 65;          // C + H
constexpr int CIN1 = 128;         // 2H
constexpr int F0   = BB * CIN0;   // 4160
constexpr int F1   = BB * CIN1;   // 8192
constexpr int KC0  = 3 * CIN0;    // 195
constexpr int KC1  = 3 * CIN1;    // 384

// ---------------- packed f32x2 helpers (sm_100+ FFMA2 path) ----------------
typedef unsigned long long u64;

__device__ __forceinline__ u64 pack2(float x, float y) {
    u64 r; asm("mov.b64 %0, {%1,%2};" : "=l"(r) : "f"(x), "f"(y)); return r;
}
__device__ __forceinline__ void unpack2(u64 v, float& x, float& y) {
    asm("mov.b64 {%0,%1}, %2;" : "=f"(x), "=f"(y) : "l"(v));
}
__device__ __forceinline__ void ffma2(u64& d, u64 a, u64 b) {
    asm("fma.rn.f32x2 %0, %1, %2, %0;" : "+l"(d) : "l"(a), "l"(b));
}

// ---------------- device scratch (static globals; no runtime allocation) ----------------
__device__ float g_A[NN * NN];                       // 16 MB
__device__ float g_gW0[NN * KC0 * 2 * HH];
__device__ float g_uW0[NN * KC0 * HH];
__device__ float g_gW1[NN * KC1 * 2 * HH];
__device__ float g_uW1[NN * KC1 * HH];
__device__ float g_gb0[NN * 2 * HH];
__device__ float g_ub0[NN * HH];
__device__ float g_gb1[NN * 2 * HH];
__device__ float g_ub1[NN * HH];
__device__ float g_xc[NN * F1];                      // x-concat, c-major [m, c*B+b]
__device__ float g_y1[NN * F1];
__device__ float g_y2[NN * F1];
__device__ float g_zr[NN * 2 * HH * BB];
__device__ float g_h0[NN * HH * BB];
__device__ float g_h1[NN * HH * BB];

// ---------------- A = softmax(relu(E E^T)) row-wise ----------------
__global__ void __launch_bounds__(256) adj_softmax_kernel(const float* __restrict__ E) {
    __shared__ float row[NN];
    __shared__ float sred[8];
    int n = blockIdx.x, tid = threadIdx.x;
    int lane = tid & 31, wid = tid >> 5;
    float en[DD];
#pragma unroll
    for (int d = 0; d < DD; d++) en[d] = E[n * DD + d];
    float lmax = 0.f;
    for (int m = tid; m < NN; m += 256) {
        const float* em = &E[m * DD];
        float s = 0.f;
#pragma unroll
        for (int d = 0; d < DD; d++) s += en[d] * em[d];
        s = fmaxf(s, 0.f);
        row[m] = s;
        lmax = fmaxf(lmax, s);
    }
#pragma unroll
    for (int off = 16; off; off >>= 1) lmax = fmaxf(lmax, __shfl_xor_sync(0xffffffffu, lmax, off));
    if (lane == 0) sred[wid] = lmax;
    __syncthreads();
    float bmax = sred[0];
#pragma unroll
    for (int w = 1; w < 8; w++) bmax = fmaxf(bmax, sred[w]);
    float lsum = 0.f;
    for (int m = tid; m < NN; m += 256) {
        float e = expf(row[m] - bmax);
        row[m] = e;
        lsum += e;
    }
#pragma unroll
    for (int off = 16; off; off >>= 1) lsum += __shfl_xor_sync(0xffffffffu, lsum, off);
    __syncthreads();
    if (lane == 0) sred[wid] = lsum;
    __syncthreads();
    float bsum = 0.f;
#pragma unroll
    for (int w = 0; w < 8; w++) bsum += sred[w];
    float inv = 1.f / bsum;
    for (int m = tid; m < NN; m += 256) g_A[(size_t)n * NN + m] = row[m] * inv;
}

// ---------------- fp32 GEMM with FFMA2 + double-buffered smem ----------------
// C = alpha * A(MxK) * B(KxNc) + beta * Cs.  K % 8 == 0, Nc % 4 == 0.
__global__ void __launch_bounds__(256) sgemm_kernel(
    const float* __restrict__ A, const float* __restrict__ B,
    const float* __restrict__ Cs, float* __restrict__ C,
    int M, int Ncols, int K, int lda, int ldb, int ldc,
    float alpha, float beta)
{
    constexpr int BM = 128, BN = 128, BK = 8;
    __shared__ float As[2][BK][BM];
    __shared__ float Bs[2][BK][BN];
    int tid = threadIdx.x;
    int bm = blockIdx.y * BM;
    int bn = blockIdx.x * BN;
    int tx = tid & 15, ty = tid >> 4;

    // acc packed over column pairs: acc2[i][p] = (C[i][2p], C[i][2p+1])
    u64 acc2[8][4];
#pragma unroll
    for (int i = 0; i < 8; i++)
#pragma unroll
        for (int p = 0; p < 4; p++) acc2[i][p] = 0ULL;

    int arow = tid >> 1;
    int acol = (tid & 1) * 4;
    int brow = tid >> 5;
    int bcol = (tid & 31) * 4;
    bool arow_ok = (bm + arow) < M;
    bool bcol_ok = (bn + bcol) < Ncols;

    // prologue: load tile 0
    float4 av = make_float4(0.f, 0.f, 0.f, 0.f);
    float4 bv = make_float4(0.f, 0.f, 0.f, 0.f);
    if (arow_ok) av = *(const float4*)&A[(size_t)(bm + arow) * lda + acol];
    if (bcol_ok) bv = *(const float4*)&B[(size_t)brow * ldb + bn + bcol];
    As[0][acol + 0][arow] = av.x;
    As[0][acol + 1][arow] = av.y;
    As[0][acol + 2][arow] = av.z;
    As[0][acol + 3][arow] = av.w;
    *(float4*)&Bs[0][brow][bcol] = bv;
    __syncthreads();

    int buf = 0;
    for (int k0 = 0; k0 < K; k0 += BK) {
        bool more = (k0 + BK) < K;
        if (more) {
            av = make_float4(0.f, 0.f, 0.f, 0.f);
            bv = make_float4(0.f, 0.f, 0.f, 0.f);
            if (arow_ok) av = *(const float4*)&A[(size_t)(bm + arow) * lda + k0 + BK + acol];
            if (bcol_ok) bv = *(const float4*)&B[(size_t)(k0 + BK + brow) * ldb + bn + bcol];
        }
#pragma unroll
        for (int kk = 0; kk < BK; kk++) {
            float a[8];
            *(float4*)&a[0] = *(const float4*)&As[buf][kk][ty * 8];
            *(float4*)&a[4] = *(const float4*)&As[buf][kk][ty * 8 + 4];
            u64 bp[4];
            const u64* bsrc = (const u64*)&Bs[buf][kk][tx * 8];
#pragma unroll
            for (int p = 0; p < 4; p++) bp[p] = bsrc[p];
#pragma unroll
            for (int i = 0; i < 8; i++) {
                u64 ad = pack2(a[i], a[i]);
#pragma unroll
                for (int p = 0; p < 4; p++) ffma2(acc2[i][p], ad, bp[p]);
            }
        }
        if (more) {
            int nb = buf ^ 1;
            As[nb][acol + 0][arow] = av.x;
            As[nb][acol + 1][arow] = av.y;
            As[nb][acol + 2][arow] = av.z;
            As[nb][acol + 3][arow] = av.w;
            *(float4*)&Bs[nb][brow][bcol] = bv;
        }
        __syncthreads();
        buf ^= 1;
    }

#pragma unroll
    for (int i = 0; i < 8; i++) {
        int row = bm + ty * 8 + i;
        if (row >= M) continue;
#pragma unroll
        for (int p = 0; p < 4; p++) {
            float v0, v1;
            unpack2(acc2[i][p], v0, v1);
            int col0 = bn + tx * 8 + 2 * p;
            if (col0 < Ncols) {
                float v = alpha * v0;
                if (beta != 0.f) v += beta * Cs[(size_t)row * ldc + col0];
                C[(size_t)row * ldc + col0] = v;
            }
            if (col0 + 1 < Ncols) {
                float v = alpha * v1;
                if (beta != 0.f) v += beta * Cs[(size_t)row * ldc + col0 + 1];
                C[(size_t)row * ldc + col0 + 1] = v;
            }
        }
    }
}

// ---------------- per-node batched GEMM + fused GRU epilogue (FFMA2) ----------------
// out[n,o,b] = act( sum_{k,c} Xg_k[n,c,b] * W[n, k*CIN+c, o] + bias[n,o] )
template <int CIN, int OUT, bool GATE>
__global__ void __launch_bounds__(256) node_gemm_kernel(
    const float* __restrict__ xg0, const float* __restrict__ xg1, const float* __restrict__ xg2,
    const float* __restrict__ W, const float* __restrict__ bias,
    float* __restrict__ zr, float* __restrict__ h)
{
    constexpr int KC = 3 * CIN;
    constexpr int F = CIN * BB;
    constexpr int OPT = OUT / 16;    // outputs per thread (8 or 4)
    constexpr int OP2 = OPT / 2;     // packed o-pairs
    __shared__ float Xs[8][BB];
    __shared__ float Ws[8][OUT];
    int n = blockIdx.x;
    int tid = threadIdx.x;
    int tx = tid & 15, ty = tid >> 4;

    // acc packed over o-pairs: acc2[p][bi] = (out[2p][bi], out[2p+1][bi])
    u64 acc2[OP2][4];
#pragma unroll
    for (int p = 0; p < OP2; p++)
#pragma unroll
        for (int bi = 0; bi < 4; bi++) acc2[p][bi] = 0ULL;

    for (int rc = 0; rc < KC; rc += 8) {
#pragma unroll
        for (int e = tid; e < 8 * BB; e += 256) {
            int i = e >> 6, b = e & 63;
            int r = rc + i;
            float v = 0.f;
            if (r < KC) {
                int k = r / CIN;
                int c = r - k * CIN;
                const float* base = (k == 0) ? xg0 : ((k == 1) ? xg1 : xg2);
                v = base[(size_t)n * F + c * BB + b];
            }
            Xs[i][b] = v;
        }
#pragma unroll
        for (int e4 = tid; e4 < 8 * OUT / 4; e4 += 256) {
            int e = e4 * 4;
            int i = e / OUT, o = e % OUT;
            int r = rc + i;
            float4 v = make_float4(0.f, 0.f, 0.f, 0.f);
            if (r < KC) v = *(const float4*)&W[((size_t)n * KC + r) * OUT + o];
            *(float4*)&Ws[i][o] = v;
        }
        __syncthreads();
#pragma unroll
        for (int i = 0; i < 8; i++) {
            float bvals[4];
            *(float4*)&bvals[0] = *(const float4*)&Xs[i][tx * 4];
            u64 wp[OP2];
            const u64* wsrc = (const u64*)&Ws[i][ty * OPT];
#pragma unroll
            for (int p = 0; p < OP2; p++) wp[p] = wsrc[p];
#pragma unroll
            for (int bi = 0; bi < 4; bi++) {
                u64 bd = pack2(bvals[bi], bvals[bi]);
#pragma unroll
                for (int p = 0; p < OP2; p++) ffma2(acc2[p][bi], wp[p], bd);
            }
        }
        __syncthreads();
    }

#pragma unroll
    for (int p = 0; p < OP2; p++) {
        int o0 = ty * OPT + 2 * p;
        float bia0 = bias[(size_t)n * OUT + o0];
        float bia1 = bias[(size_t)n * OUT + o0 + 1];
#pragma unroll
        for (int bi = 0; bi < 4; bi++) {
            int b = tx * 4 + bi;
            float v0, v1;
            unpack2(acc2[p][bi], v0, v1);
            v0 += bia0; v1 += bia1;
            if (GATE) {
                zr[((size_t)n * (2 * HH) + o0) * BB + b]     = 1.f / (1.f + expf(-v0));
                zr[((size_t)n * (2 * HH) + o0 + 1) * BB + b] = 1.f / (1.f + expf(-v1));
            } else {
                float hc0 = tanhf(v0);
                float hc1 = tanhf(v1);
                float r0 = zr[((size_t)n * (2 * HH) + HH + o0) * BB + b];
                float r1 = zr[((size_t)n * (2 * HH) + HH + o0 + 1) * BB + b];
                size_t hi0 = ((size_t)n * HH + o0) * BB + b;
                size_t hi1 = ((size_t)n * HH + o0 + 1) * BB + b;
                float hv0 = h[hi0], hv1 = h[hi1];
                h[hi0] = r0 * hv0 + (1.f - r0) * hc0;
                h[hi1] = r1 * hv1 + (1.f - r1) * hc1;
            }
        }
    }
}

// ---------------- prep kernels (build xc buffers) ----------------
__global__ void prep_xc0_kernel(const float* __restrict__ src, int t) {
    long idx = (long)blockIdx.x * blockDim.x + threadIdx.x;
    if (idx >= (long)NN * F0) return;
    int m = (int)(idx / F0);
    int col = (int)(idx - (long)m * F0);
    float v;
    if (col < BB) {
        int b = col;
        v = src[((size_t)(b * TT + t)) * NN + m];
    } else {
        v = g_h0[(size_t)m * (HH * BB) + (col - BB)];
    }
    g_xc[idx] = v;
}

__global__ void prep_xc0b_kernel() {
    long idx = (long)blockIdx.x * blockDim.x + threadIdx.x;
    if (idx >= (long)NN * HH * BB) return;
    int m = (int)(idx >> 12);
    int e = (int)(idx & 4095);
    g_xc[(size_t)m * F0 + BB + e] = g_zr[(size_t)m * (2 * HH * BB) + e] * g_h0[idx];
}

__global__ void prep_xc1_kernel() {
    long idx = (long)blockIdx.x * blockDim.x + threadIdx.x;
    if (idx >= (long)NN * F1) return;
    int m = (int)(idx >> 13);
    int e = (int)(idx & 8191);
    float v = (e < HH * BB) ? g_h0[(size_t)m * (HH * BB) + e]
                            : g_h1[(size_t)m * (HH * BB) + (e - HH * BB)];
    g_xc[idx] = v;
}

__global__ void prep_xc1b_kernel() {
    long idx = (long)blockIdx.x * blockDim.x + threadIdx.x;
    if (idx >= (long)NN * HH * BB) return;
    int m = (int)(idx >> 12);
    int e = (int)(idx & 4095);
    g_xc[(size_t)m * F1 + HH * BB + e] = g_zr[(size_t)m * (2 * HH * BB) + e] * g_h1[idx];
}

// ---------------- final projection ----------------
__global__ void __launch_bounds__(256) final_kernel(
    const float* __restrict__ cw, const float* __restrict__ cb, float* __restrict__ out)
{
    __shared__ float hs[HH * BB];
    __shared__ float cws[TT * HH];
    __shared__ float cbs[TT];
    int n = blockIdx.x, tid = threadIdx.x;
    for (int e = tid; e < HH * BB; e += 256) hs[e] = g_h1[(size_t)n * HH * BB + e];
    for (int e = tid; e < TT * HH; e += 256) cws[e] = cw[e];
    if (tid < TT) cbs[tid] = cb[tid];
    __syncthreads();
    for (int p = tid; p < BB * TT; p += 256) {
        int b = p / TT, o = p - b * TT;
        float s = cbs[o];
#pragma unroll
        for (int hh2 = 0; hh2 < HH; hh2++) s += hs[hh2 * BB + b] * cws[o * HH + hh2];
        out[((size_t)(b * TT + o)) * NN + n] = s;
    }
}

// ---------------- host orchestration ----------------
static void sgemm(const float* A, const float* B, const float* Cs, float* C,
                  int M, int Nc, int K, int lda, int ldb, int ldc,
                  float alpha, float beta)
{
    dim3 grid((Nc + 127) / 128, (M + 127) / 128);
    sgemm_kernel<<<grid, 256>>>(A, B, Cs, C, M, Nc, K, lda, ldb, ldc, alpha, beta);
}

extern "C" void kernel_launch(void* const* d_in, const int* in_sizes, int n_in,
                              void* d_out, int out_size)
{
    const float* src  = (const float*)d_in[0];
    const float* E    = (const float*)d_in[1];
    const float* gwp0 = (const float*)d_in[2];
    const float* gbp0 = (const float*)d_in[3];
    const float* uwp0 = (const float*)d_in[4];
    const float* ubp0 = (const float*)d_in[5];
    const float* gwp1 = (const float*)d_in[6];
    const float* gbp1 = (const float*)d_in[7];
    const float* uwp1 = (const float*)d_in[8];
    const float* ubp1 = (const float*)d_in[9];
    const float* cw   = (const float*)d_in[10];
    const float* cb   = (const float*)d_in[11];
    float* out = (float*)d_out;

    float *A_, *gW0_, *uW0_, *gW1_, *uW1_, *gb0_, *ub0_, *gb1_, *ub1_;
    float *xc_, *y1_, *y2_, *zr_, *h0_, *h1_;
    cudaGetSymbolAddress((void**)&A_,   g_A);
    cudaGetSymbolAddress((void**)&gW0_, g_gW0);
    cudaGetSymbolAddress((void**)&uW0_, g_uW0);
    cudaGetSymbolAddress((void**)&gW1_, g_gW1);
    cudaGetSymbolAddress((void**)&uW1_, g_uW1);
    cudaGetSymbolAddress((void**)&gb0_, g_gb0);
    cudaGetSymbolAddress((void**)&ub0_, g_ub0);
    cudaGetSymbolAddress((void**)&gb1_, g_gb1);
    cudaGetSymbolAddress((void**)&ub1_, g_ub1);
    cudaGetSymbolAddress((void**)&xc_,  g_xc);
    cudaGetSymbolAddress((void**)&y1_,  g_y1);
    cudaGetSymbolAddress((void**)&y2_,  g_y2);
    cudaGetSymbolAddress((void**)&zr_,  g_zr);
    cudaGetSymbolAddress((void**)&h0_,  g_h0);
    cudaGetSymbolAddress((void**)&h1_,  g_h1);

    cudaMemsetAsync(h0_, 0, (size_t)NN * HH * BB * sizeof(float), 0);
    cudaMemsetAsync(h1_, 0, (size_t)NN * HH * BB * sizeof(float), 0);

    adj_softmax_kernel<<<NN, 256>>>(E);

    sgemm(E, gwp0, gW0_, gW0_, NN, KC0 * 2 * HH, DD, DD, KC0 * 2 * HH, KC0 * 2 * HH, 1.f, 0.f);
    sgemm(E, uwp0, uW0_, uW0_, NN, KC0 * HH,     DD, DD, KC0 * HH,     KC0 * HH,     1.f, 0.f);
    sgemm(E, gwp1, gW1_, gW1_, NN, KC1 * 2 * HH, DD, DD, KC1 * 2 * HH, KC1 * 2 * HH, 1.f, 0.f);
    sgemm(E, uwp1, uW1_, uW1_, NN, KC1 * HH,     DD, DD, KC1 * HH,     KC1 * HH,     1.f, 0.f);
    sgemm(E, gbp0, gb0_, gb0_, NN, 2 * HH, DD, DD, 2 * HH, 2 * HH, 1.f, 0.f);
    sgemm(E, ubp0, ub0_, ub0_, NN, HH,     DD, DD, HH,     HH,     1.f, 0.f);
    sgemm(E, gbp1, gb1_, gb1_, NN, 2 * HH, DD, DD, 2 * HH, 2 * HH, 1.f, 0.f);
    sgemm(E, ubp1, ub1_, ub1_, NN, HH,     DD, DD, HH,     HH,     1.f, 0.f);

    const int PB = 256;
    for (int t = 0; t < TT; t++) {
        // ===== layer 0 =====
        prep_xc0_kernel<<<(int)(((long)NN * F0 + PB - 1) / PB), PB>>>(src, t);
        sgemm(A_, xc_, xc_, y1_, NN, F0, NN, NN, F0, F0, 1.f, 0.f);
        sgemm(A_, y1_, xc_, y2_, NN, F0, NN, NN, F0, F0, 2.f, -1.f);
        node_gemm_kernel<CIN0, 2 * HH, true><<<NN, 256>>>(xc_, y1_, y2_, gW0_, gb0_, zr_, h0_);
        prep_xc0b_kernel<<<(int)(((long)NN * HH * BB + PB - 1) / PB), PB>>>();
        sgemm(A_, xc_ + BB, xc_ + BB, y1_ + BB, NN, F0 - BB, NN, NN, F0, F0, 1.f, 0.f);
        sgemm(A_, y1_ + BB, xc_ + BB, y2_ + BB, NN, F0 - BB, NN, NN, F0, F0, 2.f, -1.f);
        node_gemm_kernel<CIN0, HH, false><<<NN, 256>>>(xc_, y1_, y2_, uW0_, ub0_, zr_, h0_);

        // ===== layer 1 =====
        prep_xc1_kernel<<<(int)(((long)NN * F1 + PB - 1) / PB), PB>>>();
        sgemm(A_, xc_, xc_, y1_, NN, F1, NN, NN, F1, F1, 1.f, 0.f);
        sgemm(A_, y1_, xc_, y2_, NN, F1, NN, NN, F1, F1, 2.f, -1.f);
        node_gemm_kernel<CIN1, 2 * HH, true><<<NN, 256>>>(xc_, y1_, y2_, gW1_, gb1_, zr_, h1_);
        prep_xc1b_kernel<<<(int)(((long)NN * HH * BB + PB - 1) / PB), PB>>>();
        sgemm(A_, xc_ + HH * BB, xc_ + HH * BB, y1_ + HH * BB, NN, F1 - HH * BB, NN, NN, F1, F1, 1.f, 0.f);
        sgemm(A_, y1_ + HH * BB, xc_ + HH * BB, y2_ + HH * BB, NN, F1 - HH * BB, NN, NN, F1, F1, 2.f, -1.f);
        node_gemm_kernel<CIN1, HH, false><<<NN, 256>>>(xc_, y1_, y2_, uW1_, ub1_, zr_, h1_);
    }

    final_kernel<<<NN, 256>>>(cw, cb, out);
}